// round 10
// baseline (speedup 1.0000x reference)
#include <cuda_runtime.h>
#include <cstdint>
#include <cstddef>

// Problem constants
#define T_DIM 1024
#define M_DIM 128
#define A_DIM 64
#define D_DIM 128
#define NTHREADS 256

// ---------------- global scratch ----------------
// Packed weights (filled once per launch by pack_weights).
// B-operand packed layout: entry (nt, ksp, slot) holds float4
//   e0 = B[16*ksp + q    ][8*nt + g]
//   e1 = B[16*ksp + q + 4][8*nt + g]
//   e2 = B[16*ksp + q + 8][8*nt + g]
//   e3 = B[16*ksp + q +12][8*nt + g]
// for consumer lane (g,q) stored at slot = g*4 + ((q + (g>>1)) & 3).
__device__ float g_W1p[16 * 4 * 32 * 4];   // W1: K=64  -> KSP=4   (8192 floats)
__device__ float g_W2p[16 * 8 * 32 * 4];   // W2: K=128 -> KSP=8   (16384 floats)

// Packed S scratch: per t, GEMM3 B-operand fragment layout (16384 floats = 64KB)
#define SP_STRIDE 16384
__device__ float g_Sp[(size_t)T_DIM * SP_STRIDE];   // 64 MB

// ---------------- helpers ----------------
__device__ __forceinline__ unsigned f2tf32(float x) {
    unsigned u;
    asm("cvt.rna.tf32.f32 %0, %1;" : "=r"(u) : "f"(x));
    return u;
}
__device__ __forceinline__ float tf32f(float x) { return __uint_as_float(f2tf32(x)); }

// lane-slot permutation within a 32-lane packed group (bank spreading)
__device__ __forceinline__ int slot_of(int g, int q) { return g * 4 + ((q + (g >> 1)) & 3); }
__device__ __forceinline__ void inv_slot(int j, int& g, int& q) {
    g = j >> 2;
    q = ((j & 3) + 4 - ((g >> 1) & 3)) & 3;
}

__device__ __forceinline__ void mma_tf32(float c[4],
                                         unsigned a0, unsigned a1, unsigned a2, unsigned a3,
                                         unsigned b0, unsigned b1) {
    asm volatile(
        "mma.sync.aligned.m16n8k8.row.col.f32.tf32.tf32.f32 "
        "{%0,%1,%2,%3}, {%4,%5,%6,%7}, {%8,%9}, {%0,%1,%2,%3};"
        : "+f"(c[0]), "+f"(c[1]), "+f"(c[2]), "+f"(c[3])
        : "r"(a0), "r"(a1), "r"(a2), "r"(a3), "r"(b0), "r"(b1));
}

// ---------------- setup kernel: pack W1/W2 into fragment layout --------------
__global__ void pack_weights(const float* __restrict__ W1, const float* __restrict__ W2) {
    const int idx = blockIdx.x * 256 + threadIdx.x;   // 6144 total
    if (idx < 2048) {                                  // W1p: nt(16) x ksp(4) x slot(32)
        const int js = idx & 31, ksp = (idx >> 5) & 3, nt = idx >> 7;
        int g, q; inv_slot(js, g, q);
        const int n = nt * 8 + g, k0 = ksp * 16 + q;
        float4 v;
        v.x = tf32f(W1[(k0     ) * D_DIM + n]);
        v.y = tf32f(W1[(k0 +  4) * D_DIM + n]);
        v.z = tf32f(W1[(k0 +  8) * D_DIM + n]);
        v.w = tf32f(W1[(k0 + 12) * D_DIM + n]);
        *reinterpret_cast<float4*>(&g_W1p[idx * 4]) = v;
    } else {                                           // W2p: nt(16) x ksp(8) x slot(32)
        const int i2 = idx - 2048;
        const int js = i2 & 31, ksp = (i2 >> 5) & 7, nt = i2 >> 8;
        int g, q; inv_slot(js, g, q);
        const int n = nt * 8 + g, k0 = ksp * 16 + q;
        float4 v;
        v.x = tf32f(W2[(k0     ) * M_DIM + n]);
        v.y = tf32f(W2[(k0 +  4) * M_DIM + n]);
        v.z = tf32f(W2[(k0 +  8) * M_DIM + n]);
        v.w = tf32f(W2[(k0 + 12) * M_DIM + n]);
        *reinterpret_cast<float4*>(&g_W2p[i2 * 4]) = v;
    }
}

// ---------------- packed-fragment GEMM: warp computes 64x32 tile --------------------
// A packed (smem): entry (rg, ks, slot) float4 = {A[16rg+g][8ks+q], A[16rg+g+8][8ks+q],
//                                                 A[16rg+g][8ks+q+4], A[16rg+g+8][8ks+q+4]}
// B packed (smem or global): entry (nt, ksp, slot) as documented above.
// Warp owns rows [64*rg2, 64*rg2+64), cols [32*cg, 32*cg+32).
// Register-lean ordering: A fragments loaded per-ksp, B loaded per-ntl just before use.
template<int KSP>
__device__ __forceinline__ void gemm64(const float* __restrict__ PA,
                                       const float* __restrict__ PB,
                                       int rg2, int cg, int slotl,
                                       float acc[4][4][4]) {
    #pragma unroll
    for (int ksp = 0; ksp < KSP; ksp++) {
        float4 aE[4], aO[4];
        #pragma unroll
        for (int rgl = 0; rgl < 4; rgl++) {
            const int rg = 4 * rg2 + rgl;
            aE[rgl] = *reinterpret_cast<const float4*>(
                &PA[((rg * (2 * KSP) + 2 * ksp    ) * 32 + slotl) * 4]);
            aO[rgl] = *reinterpret_cast<const float4*>(
                &PA[((rg * (2 * KSP) + 2 * ksp + 1) * 32 + slotl) * 4]);
        }
        #pragma unroll
        for (int ntl = 0; ntl < 4; ntl++) {
            const float4 b = *reinterpret_cast<const float4*>(
                &PB[(((4 * cg + ntl) * KSP + ksp) * 32 + slotl) * 4]);
            #pragma unroll
            for (int rgl = 0; rgl < 4; rgl++) {
                mma_tf32(acc[rgl][ntl],
                         __float_as_uint(aE[rgl].x), __float_as_uint(aE[rgl].y),
                         __float_as_uint(aE[rgl].z), __float_as_uint(aE[rgl].w),
                         __float_as_uint(b.x), __float_as_uint(b.y));
                mma_tf32(acc[rgl][ntl],
                         __float_as_uint(aO[rgl].x), __float_as_uint(aO[rgl].y),
                         __float_as_uint(aO[rgl].z), __float_as_uint(aO[rgl].w),
                         __float_as_uint(b.z), __float_as_uint(b.w));
            }
        }
    }
}

__device__ __forceinline__ void zero_acc(float acc[4][4][4]) {
    #pragma unroll
    for (int a = 0; a < 4; a++)
        #pragma unroll
        for (int n = 0; n < 4; n++)
            #pragma unroll
            for (int r = 0; r < 4; r++) acc[a][n][r] = 0.0f;
}

// ================= Kernel A: MLP  (S_t packed -> g_Sp) =================
// SMEM: Xp [0,8192) floats; Hp/Sp union [8192,24576); b1 [24576,24704); b2 [24704,24832)
#define A_XP   0
#define A_HP   8192
#define A_SP   8192
#define A_B1O  24576
#define A_B2O  24704
#define A_SMEM_FLOATS 24832
#define A_SMEM_BYTES  (A_SMEM_FLOATS * 4)   // 99328

__global__ __launch_bounds__(NTHREADS, 2)
void slam_mlp_kernel(const float* __restrict__ x_aux,
                     const float* __restrict__ b1,
                     const float* __restrict__ b2) {
    extern __shared__ float sm[];
    const int t    = blockIdx.x;
    const int tid  = threadIdx.x;
    const int warp = tid >> 5;
    const int lane = tid & 31;
    const int g    = lane >> 2;
    const int q    = lane & 3;
    const int rg2  = warp >> 2;   // 0..1
    const int cg   = warp & 3;    // 0..3
    const int slotl = slot_of(g, q);

    // stage Xp (packed-A gather), biases
    {
        const float* xp = x_aux + (size_t)t * A_DIM;
        #pragma unroll
        for (int it = 0; it < 8; it++) {
            const int idx = tid + it * NTHREADS;            // 2048 entries
            const int js = idx & 31, ks = (idx >> 5) & 7, rg = idx >> 8;
            int gg, qq; inv_slot(js, gg, qq);
            const int r0 = rg * 16 + gg, c0 = ks * 8 + qq;
            const size_t rs = (size_t)(T_DIM * A_DIM);
            float4 v;
            v.x = tf32f(xp[(size_t)(r0    ) * rs + c0    ]);
            v.y = tf32f(xp[(size_t)(r0 + 8) * rs + c0    ]);
            v.z = tf32f(xp[(size_t)(r0    ) * rs + c0 + 4]);
            v.w = tf32f(xp[(size_t)(r0 + 8) * rs + c0 + 4]);
            *reinterpret_cast<float4*>(&sm[A_XP + idx * 4]) = v;
        }
        if (tid < 128) {
            sm[A_B1O + tid] = b1[tid];
            sm[A_B2O + tid] = b2[tid];
        }
    }
    __syncthreads();

    float acc[4][4][4];
    const int hi  = (q >= 2) ? 2 : 0;
    const int qc0 = (2 * q) & 3;

    // GEMM1: H = relu(X @ W1 + b1)   (B from global, L1/L2-cached)
    zero_acc(acc);
    gemm64<4>(&sm[A_XP], g_W1p, rg2, cg, slotl, acc);

    // epilogue1 -> Hp (packed-A for GEMM2, KS=16)
    #pragma unroll
    for (int rgl = 0; rgl < 4; rgl++) {
        const int rg = 4 * rg2 + rgl;
        #pragma unroll
        for (int ntl = 0; ntl < 4; ntl++) {
            const int ks = 4 * cg + ntl;
            const int d0 = 32 * cg + 8 * ntl + 2 * q;
            const float bb0 = sm[A_B1O + d0], bb1 = sm[A_B1O + d0 + 1];
            const int base = A_HP + (rg * 16 + ks) * 128;
            const int s0 = slot_of(g, qc0), s1 = slot_of(g, qc0 + 1);
            float2 w0, w1;
            w0.x = tf32f(fmaxf(acc[rgl][ntl][0] + bb0, 0.0f));
            w0.y = tf32f(fmaxf(acc[rgl][ntl][2] + bb0, 0.0f));
            w1.x = tf32f(fmaxf(acc[rgl][ntl][1] + bb1, 0.0f));
            w1.y = tf32f(fmaxf(acc[rgl][ntl][3] + bb1, 0.0f));
            *reinterpret_cast<float2*>(&sm[base + s0 * 4 + hi]) = w0;
            *reinterpret_cast<float2*>(&sm[base + s1 * 4 + hi]) = w1;
        }
    }
    __syncthreads();

    // GEMM2: S = H @ W2 + b2   (B from global)
    zero_acc(acc);
    gemm64<8>(&sm[A_HP], g_W2p, rg2, cg, slotl, acc);
    __syncthreads();   // all Hp reads done before Sp overwrite

    // epilogue2 -> Sp (packed-B for GEMM3; k-dim = j = GEMM2 output row)
    #pragma unroll
    for (int rgl = 0; rgl < 4; rgl++) {
        const int ksp = 4 * rg2 + rgl;    // j>>4
        const int e0  = g >> 2;
        #pragma unroll
        for (int ntl = 0; ntl < 4; ntl++) {
            const int nt = 4 * cg + ntl;
            const int n0 = 32 * cg + 8 * ntl + 2 * q;
            const float bb0 = sm[A_B2O + n0], bb1 = sm[A_B2O + n0 + 1];
            const int base = A_SP + (nt * 8 + ksp) * 128;
            const int s0 = slot_of(2 * q,     g & 3);
            const int s1 = slot_of(2 * q + 1, g & 3);
            sm[base + s0 * 4 + e0    ] = tf32f(acc[rgl][ntl][0] + bb0);  // (j0,n0)
            sm[base + s1 * 4 + e0    ] = tf32f(acc[rgl][ntl][1] + bb1);  // (j0,n1)
            sm[base + s0 * 4 + e0 + 2] = tf32f(acc[rgl][ntl][2] + bb0);  // (j1,n0)
            sm[base + s1 * 4 + e0 + 2] = tf32f(acc[rgl][ntl][3] + bb1);  // (j1,n1)
        }
    }
    __syncthreads();

    // coalesced copy Sp -> g_Sp[t]
    {
        const float4* src = reinterpret_cast<const float4*>(&sm[A_SP]);
        float4* dst = reinterpret_cast<float4*>(g_Sp + (size_t)t * SP_STRIDE);
        #pragma unroll
        for (int it = 0; it < 16; it++) {
            const int i = tid + it * NTHREADS;   // 4096 float4
            dst[i] = src[i];
        }
    }
}

// ================= Kernel B: out_t = Main_t @ S_t =================
// SMEM: Mainp [0,16384) floats
#define B_SMEM_FLOATS 16384
#define B_SMEM_BYTES  (B_SMEM_FLOATS * 4)   // 65536

__global__ __launch_bounds__(NTHREADS, 2)
void slam_out_kernel(const float* __restrict__ x_main_last,
                     float* __restrict__ out) {
    extern __shared__ float sm[];
    const int t    = blockIdx.x;
    const int tid  = threadIdx.x;
    const int warp = tid >> 5;
    const int lane = tid & 31;
    const int g    = lane >> 2;
    const int q    = lane & 3;
    const int rg2  = warp >> 2;   // 0..1
    const int cg   = warp & 3;    // 0..3
    const int slotl = slot_of(g, q);

    // stage Mainp (packed-A)
    {
        const float* mp = x_main_last + (size_t)t * (M_DIM * M_DIM);
        #pragma unroll
        for (int it = 0; it < 16; it++) {
            const int idx = tid + it * NTHREADS;            // 4096 entries
            const int js = idx & 31, ks = (idx >> 5) & 15, rg = idx >> 9;
            int gg, qq; inv_slot(js, gg, qq);
            const int r0 = rg * 16 + gg, c0 = ks * 8 + qq;
            float4 v;
            v.x = tf32f(mp[(r0    ) * M_DIM + c0    ]);
            v.y = tf32f(mp[(r0 + 8) * M_DIM + c0    ]);
            v.z = tf32f(mp[(r0    ) * M_DIM + c0 + 4]);
            v.w = tf32f(mp[(r0 + 8) * M_DIM + c0 + 4]);
            *reinterpret_cast<float4*>(&sm[idx * 4]) = v;
        }
    }
    __syncthreads();

    // GEMM3: A = Mainp (smem), B = packed S_t (global, L1-reused x2)
    float acc[4][4][4];
    zero_acc(acc);
    gemm64<8>(sm, g_Sp + (size_t)t * SP_STRIDE, rg2, cg, slotl, acc);

    // epilogue -> gmem
    float* op = out + (size_t)t * (M_DIM * M_DIM);
    #pragma unroll
    for (int rgl = 0; rgl < 4; rgl++) {
        const int i0 = 64 * rg2 + 16 * rgl + g;
        #pragma unroll
        for (int ntl = 0; ntl < 4; ntl++) {
            const int c0 = 32 * cg + 8 * ntl + 2 * q;
            float2 v0 = make_float2(acc[rgl][ntl][0], acc[rgl][ntl][1]);
            float2 v1 = make_float2(acc[rgl][ntl][2], acc[rgl][ntl][3]);
            *reinterpret_cast<float2*>(op + (size_t)(i0    ) * M_DIM + c0) = v0;
            *reinterpret_cast<float2*>(op + (size_t)(i0 + 8) * M_DIM + c0) = v1;
        }
    }
}

extern "C" void kernel_launch(void* const* d_in, const int* in_sizes, int n_in,
                              void* d_out, int out_size) {
    const float* x_main = (const float*)d_in[0];
    const float* x_aux  = (const float*)d_in[1];
    const float* W1     = (const float*)d_in[2];
    const float* b1     = (const float*)d_in[3];
    const float* W2     = (const float*)d_in[4];
    const float* b2     = (const float*)d_in[5];
    float* out = (float*)d_out;

    // last batch of x_main: x_main[N-1, :, 0, :, :]
    const size_t slice = (size_t)T_DIM * M_DIM * M_DIM;
    const float* x_main_last = x_main + ((size_t)in_sizes[0] - slice);

    cudaFuncSetAttribute(slam_mlp_kernel,
                         cudaFuncAttributeMaxDynamicSharedMemorySize, A_SMEM_BYTES);
    cudaFuncSetAttribute(slam_out_kernel,
                         cudaFuncAttributeMaxDynamicSharedMemorySize, B_SMEM_BYTES);

    pack_weights<<<24, 256>>>(W1, W2);
    slam_mlp_kernel<<<T_DIM, NTHREADS, A_SMEM_BYTES>>>(x_aux, b1, b2);
    slam_out_kernel<<<T_DIM, NTHREADS, B_SMEM_BYTES>>>(x_main_last, out);
}